// round 10
// baseline (speedup 1.0000x reference)
#include <cuda_runtime.h>
#include <cuda_bf16.h>
#include <math.h>
#include <stdint.h>

#define B_   2
#define T_   2048
#define DIM_ 4096
#define NH   32
#define NKV  8
#define HD   128
#define RG   (NH / NKV)
#define K2   (2 * DIM_)          // paired hi/lo row length (8192 elems)

#define QSCALE 0.08838834764831843f  // 1/sqrt(128)

typedef __nv_bfloat16 bf16;

// ---------------- scratch (allocation-free: __device__ globals) ----------------
// paired hi/lo layouts: per 32-K block, 32 hi then 32 lo (64 elems, 128B)
__device__ bf16 g_xp [(size_t)(B_*T_) * K2];                    // x
__device__ bf16 g_wp [(size_t)(DIM_ + 2*NKV*HD) * K2];          // Wq ++ Wkv
__device__ bf16 g_op [(size_t)(B_*T_) * K2];                    // attention out (paired)
__device__ bf16 g_wop[(size_t)DIM_ * K2];                       // Wo

// hi/lo split bf16 Q,K,V (written by QKV-GEMM epilogue, read by flash)
__device__ bf16 g_qh[(size_t)B_ * NH  * T_ * HD];
__device__ bf16 g_ql[(size_t)B_ * NH  * T_ * HD];
__device__ bf16 g_kh[(size_t)B_ * NKV * T_ * HD];
__device__ bf16 g_kl[(size_t)B_ * NKV * T_ * HD];
__device__ bf16 g_vh[(size_t)B_ * NKV * T_ * HD];
__device__ bf16 g_vl[(size_t)B_ * NKV * T_ * HD];

// ---------------- fp32 -> paired hi/lo bf16 ----------------
// block i (32 floats) -> out[i*64 .. i*64+32) = hi, [i*64+32 .. +64) = lo
__global__ void __launch_bounds__(256)
conv_pair(const float* __restrict__ in, bf16* __restrict__ out, int nblk)
{
    int i = blockIdx.x * 256 + threadIdx.x;
    if (i >= nblk) return;
    const float4* src = (const float4*)(in + (size_t)i * 32);
    __align__(16) bf16 h[32], l[32];
#pragma unroll
    for (int q = 0; q < 8; q++) {
        float4 f = src[q];
        float vv[4] = {f.x, f.y, f.z, f.w};
#pragma unroll
        for (int j = 0; j < 4; j++) {
            bf16 hi = __float2bfloat16_rn(vv[j]);
            h[q*4+j] = hi;
            l[q*4+j] = __float2bfloat16_rn(vv[j] - __bfloat162float(hi));
        }
    }
    uint4* dst = (uint4*)(out + (size_t)i * 64);
#pragma unroll
    for (int q = 0; q < 4; q++) dst[q]     = ((uint4*)h)[q];
#pragma unroll
    for (int q = 0; q < 4; q++) dst[4 + q] = ((uint4*)l)[q];
}

// ---------------- mma / async helpers ----------------
__device__ __forceinline__ void ldsm_x4(uint32_t addr, uint32_t& r0, uint32_t& r1,
                                        uint32_t& r2, uint32_t& r3)
{
    asm volatile("ldmatrix.sync.aligned.m8n8.x4.shared.b16 {%0,%1,%2,%3}, [%4];"
                 : "=r"(r0), "=r"(r1), "=r"(r2), "=r"(r3) : "r"(addr));
}
__device__ __forceinline__ void ldsm_x4_t(uint32_t addr, uint32_t& r0, uint32_t& r1,
                                          uint32_t& r2, uint32_t& r3)
{
    asm volatile("ldmatrix.sync.aligned.m8n8.x4.trans.shared.b16 {%0,%1,%2,%3}, [%4];"
                 : "=r"(r0), "=r"(r1), "=r"(r2), "=r"(r3) : "r"(addr));
}
__device__ __forceinline__ void mma_bf16(float* c, const uint32_t* a, const uint32_t* b)
{
    asm volatile("mma.sync.aligned.m16n8k16.row.col.f32.bf16.bf16.f32 "
                 "{%0,%1,%2,%3}, {%4,%5,%6,%7}, {%8,%9}, {%0,%1,%2,%3};"
                 : "+f"(c[0]), "+f"(c[1]), "+f"(c[2]), "+f"(c[3])
                 : "r"(a[0]), "r"(a[1]), "r"(a[2]), "r"(a[3]), "r"(b[0]), "r"(b[1]));
}
__device__ __forceinline__ uint32_t pk2(float a, float b)
{
    __nv_bfloat162 t; t.x = __float2bfloat16_rn(a); t.y = __float2bfloat16_rn(b);
    return *reinterpret_cast<uint32_t*>(&t);
}
__device__ __forceinline__ void cp_async16(uint32_t dst, const void* src)
{
    asm volatile("cp.async.cg.shared.global [%0], [%1], 16;" :: "r"(dst), "l"(src));
}
__device__ __forceinline__ void cp_commit() { asm volatile("cp.async.commit_group;"); }
__device__ __forceinline__ void cp_wait2()  { asm volatile("cp.async.wait_group 2;"); }

// ---------------- epilogue stores ----------------
__device__ __forceinline__ void store_hl(bf16* __restrict__ hi, bf16* __restrict__ lo,
                                         size_t idx, float v0, float v1)
{
    bf16 h0 = __float2bfloat16_rn(v0), h1 = __float2bfloat16_rn(v1);
    bf16 e0 = __float2bfloat16_rn(v0 - __bfloat162float(h0));
    bf16 e1 = __float2bfloat16_rn(v1 - __bfloat162float(h1));
    __nv_bfloat162 H; H.x = h0; H.y = h1;
    __nv_bfloat162 L; L.x = e0; L.y = e1;
    *(__nv_bfloat162*)(hi + idx) = H;
    *(__nv_bfloat162*)(lo + idx) = L;
}

__device__ __forceinline__ void scatter2(int m, int n, float v0, float v1,
                                         bf16* qh, bf16* ql, bf16* kh, bf16* kl,
                                         bf16* vh, bf16* vl)
{
    const int bb = m >> 11;
    const int t  = m & (T_ - 1);
    if (n < DIM_) {
        size_t idx = (((size_t)bb * NH + (n >> 7)) * T_ + t) * HD + (n & 127);
        store_hl(qh, ql, idx, v0 * QSCALE, v1 * QSCALE);
    } else {
        int cc = n - DIM_;
        if (cc < NKV * HD) {
            size_t idx = (((size_t)bb * NKV + (cc >> 7)) * T_ + t) * HD + (cc & 127);
            store_hl(kh, kl, idx, v0, v1);
        } else {
            cc -= NKV * HD;
            size_t idx = (((size_t)bb * NKV + (cc >> 7)) * T_ + t) * HD + (cc & 127);
            store_hl(vh, vl, idx, v0, v1);
        }
    }
}

// ---------------- tensor-core compensated GEMM: C = A @ W^T ----------------
// Paired hi/lo operands, real K = 4096, BK = 32 real K per stage.
// Per frag set: acc += ah*bh + al*bh + ah*bl  (== validated triple-K math).
// Stage: A tile 16KB + W tile 16KB = 32KB; STAGES=4 -> 128KB smem, cp.async pipeline.
#define STAGES 4

template <int MODE>
__global__ void __launch_bounds__(256)
mma_gemm2(const bf16* __restrict__ Ap, const bf16* __restrict__ Wp,
          float* __restrict__ outC,
          bf16* qh, bf16* ql, bf16* kh, bf16* kl, bf16* vh, bf16* vl)
{
    extern __shared__ __align__(16) unsigned char smem[];   // STAGES * 32KB

    const int tid  = threadIdx.x;
    const int lane = tid & 31;
    const int w    = tid >> 5;
    const int wm   = w & 1;          // 2 warps in M
    const int wn   = w >> 1;         // 4 warps in N
    const int m0   = blockIdx.y * 128;
    const int n0   = blockIdx.x * 128;

    const uint32_t sbase = (uint32_t)__cvta_generic_to_shared(smem);

    // loader: thread -> row lr (0..127), chunk range [half*4, half*4+4)
    const int lr   = tid >> 1;
    const int half = tid & 1;
    const bf16* Ag = Ap + (size_t)(m0 + lr) * K2;
    const bf16* Wg = Wp + (size_t)(n0 + lr) * K2;

    auto issue = [&](int s) {
        const uint32_t st = sbase + (uint32_t)(s & (STAGES - 1)) * 32768u;
        const size_t gofs = (size_t)s * 64;   // 64 elems per 32-K paired block
#pragma unroll
        for (int c = half * 4; c < half * 4 + 4; c++) {
            const uint32_t d = st + lr * 128 + ((c ^ (lr & 7)) << 4);
            cp_async16(d,         Ag + gofs + c * 8);
            cp_async16(d + 16384, Wg + gofs + c * 8);
        }
    };

    float acc[4][4][4];
#pragma unroll
    for (int i = 0; i < 4; i++)
#pragma unroll
        for (int j = 0; j < 4; j++)
#pragma unroll
            for (int e = 0; e < 4; e++) acc[i][j][e] = 0.f;

    issue(0); cp_commit();
    issue(1); cp_commit();
    issue(2); cp_commit();

    const int rA  = lane & 15;
    const int cAh = lane >> 4;
    const int rB  = (lane & 7) + ((lane >> 4) << 3);
    const int cBh = (lane >> 3) & 1;

    const int NK = DIM_ / 32;   // 128 stages
    for (int s = 0; s < NK; s++) {
        cp_wait2();
        __syncthreads();
        if (s + 3 < NK) issue(s + 3);
        cp_commit();

        const uint32_t sa = sbase + (uint32_t)(s & (STAGES - 1)) * 32768u;
        const uint32_t sw = sa + 16384;

#pragma unroll
        for (int kk = 0; kk < 2; kk++) {
            uint32_t ah[4][4], al[4][4], bh[4][2], bl[4][2];
#pragma unroll
            for (int mi = 0; mi < 4; mi++) {
                const int row = wm * 64 + mi * 16 + rA;
                const int chh = kk * 2 + cAh;         // hi chunks 0..3
                const uint32_t rbase = sa + row * 128;
                const int rx = row & 7;
                ldsm_x4(rbase + ((chh ^ rx) << 4),       ah[mi][0], ah[mi][1], ah[mi][2], ah[mi][3]);
                ldsm_x4(rbase + (((chh + 4) ^ rx) << 4), al[mi][0], al[mi][1], al[mi][2], al[mi][3]);
            }
#pragma unroll
            for (int np = 0; np < 2; np++) {
                const int row = wn * 32 + np * 16 + rB;
                const int chh = kk * 2 + cBh;
                const uint32_t rbase = sw + row * 128;
                const int rx = row & 7;
                uint32_t r0, r1, r2, r3;
                ldsm_x4(rbase + ((chh ^ rx) << 4), r0, r1, r2, r3);
                bh[np*2][0] = r0; bh[np*2][1] = r1; bh[np*2+1][0] = r2; bh[np*2+1][1] = r3;
                ldsm_x4(rbase + (((chh + 4) ^ rx) << 4), r0, r1, r2, r3);
                bl[np*2][0] = r0; bl[np*2][1] = r1; bl[np*2+1][0] = r2; bl[np*2+1][1] = r3;
            }
#pragma unroll
            for (int mi = 0; mi < 4; mi++)
#pragma unroll
                for (int ni = 0; ni < 4; ni++) {
                    mma_bf16(acc[mi][ni], ah[mi], bh[ni]);
                    mma_bf16(acc[mi][ni], al[mi], bh[ni]);
                    mma_bf16(acc[mi][ni], ah[mi], bl[ni]);
                }
        }
    }

    const int er = lane >> 2;
    const int ec = (lane & 3) * 2;
#pragma unroll
    for (int mi = 0; mi < 4; mi++) {
        const int m = m0 + wm * 64 + mi * 16 + er;
#pragma unroll
        for (int ni = 0; ni < 4; ni++) {
            const int n = n0 + wn * 32 + ni * 8 + ec;
            if (MODE == 1) {
                *(float2*)(outC + (size_t)m * DIM_ + n)       = make_float2(acc[mi][ni][0], acc[mi][ni][1]);
                *(float2*)(outC + (size_t)(m + 8) * DIM_ + n) = make_float2(acc[mi][ni][2], acc[mi][ni][3]);
            } else {
                scatter2(m,     n, acc[mi][ni][0], acc[mi][ni][1], qh, ql, kh, kl, vh, vl);
                scatter2(m + 8, n, acc[mi][ni][2], acc[mi][ni][3], qh, ql, kh, kl, vh, vl);
            }
        }
    }
}

// ---------------- tensor-core flash attention (compensated bf16) ----------------
// Br=128 (8 warps x 16 rows), Bc=64, hd=128.
// S = qh*kh + ql*kh + qh*kl ; O += ph*vh + pl*vh + ph*vl
// smem: Qh 32K | Ql 32K | Kh 16K | Kl 16K | Vh 16K | Vl 16K = 128KB
#define FL_SMEM 131072

__global__ void __launch_bounds__(256)
flash_mma(const bf16* __restrict__ Qh, const bf16* __restrict__ Ql,
          const bf16* __restrict__ Kh, const bf16* __restrict__ Kl,
          const bf16* __restrict__ Vh, const bf16* __restrict__ Vl,
          bf16* __restrict__ Op)      // paired hi/lo output for O-projection
{
    extern __shared__ __align__(16) unsigned char sm[];
    const uint32_t sb  = (uint32_t)__cvta_generic_to_shared(sm);
    const uint32_t bQh = sb, bQl = sb + 32768;
    const uint32_t bKh = sb + 65536, bKl = sb + 81920;
    const uint32_t bVh = sb + 98304, bVl = sb + 114688;

    const int qt = blockIdx.x, h = blockIdx.y, b = blockIdx.z;
    const int g  = h / RG;
    const int tid = threadIdx.x, lane = tid & 31, wr = tid >> 5;

    // ---- load Q tile (hi+lo), swizzled rows of 256B / 16 chunks ----
    {
        const bf16* qhg = Qh + (((size_t)b * NH + h) * T_ + (size_t)qt * 128) * HD;
        const bf16* qlg = Ql + (((size_t)b * NH + h) * T_ + (size_t)qt * 128) * HD;
#pragma unroll
        for (int u = 0; u < 8; u++) {
            const int s = tid + 256 * u;
            const int row = s >> 4, ch = s & 15;
            const int so = row * 256 + ((ch ^ (row & 7)) << 4);
            const int go = row * HD + ch * 8;
            *(uint4*)(sm + so)         = *(const uint4*)(qhg + go);
            *(uint4*)(sm + 32768 + so) = *(const uint4*)(qlg + go);
        }
    }

    float oacc[16][4];
#pragma unroll
    for (int i = 0; i < 16; i++)
#pragma unroll
        for (int e = 0; e < 4; e++) oacc[i][e] = 0.f;
    float m0 = -1e30f, m1 = -1e30f, l0 = 0.f, l1 = 0.f;

    const int arow = wr * 16 + (lane & 15);
    const int axh  = lane >> 4;
    const int bxh  = (lane >> 3) & 1;
    const int brow_base = (lane & 7) + ((lane >> 4) << 3);
    const int rowg0 = qt * 128 + wr * 16 + (lane >> 2);

    const bf16* khg = Kh + (((size_t)b * NKV + g) * T_) * HD;
    const bf16* klg = Kl + (((size_t)b * NKV + g) * T_) * HD;
    const bf16* vhg = Vh + (((size_t)b * NKV + g) * T_) * HD;
    const bf16* vlg = Vl + (((size_t)b * NKV + g) * T_) * HD;

    const int ktmax = 2 * qt + 1;
    for (int kt = 0; kt <= ktmax; kt++) {
        __syncthreads();
        {
            const size_t base = (size_t)kt * 64 * HD;
#pragma unroll
            for (int u = 0; u < 4; u++) {
                const int s = tid + 256 * u;
                const int row = s >> 4, ch = s & 15;
                const int so = row * 256 + ((ch ^ (row & 7)) << 4);
                const size_t go = base + row * HD + ch * 8;
                *(uint4*)(sm + 65536  + so) = *(const uint4*)(khg + go);
                *(uint4*)(sm + 81920  + so) = *(const uint4*)(klg + go);
                *(uint4*)(sm + 98304  + so) = *(const uint4*)(vhg + go);
                *(uint4*)(sm + 114688 + so) = *(const uint4*)(vlg + go);
            }
        }
        __syncthreads();

        if (kt * 64 > qt * 128 + wr * 16 + 15) continue;

        // ---- S = Q K^T (3 compensated passes) ----
        float s[8][4];
#pragma unroll
        for (int nf = 0; nf < 8; nf++)
#pragma unroll
            for (int e = 0; e < 4; e++) s[nf][e] = 0.f;

#pragma unroll
        for (int kk = 0; kk < 8; kk++) {
            uint32_t qhf[4], qlf[4], bh[8][2], bl[8][2];
            {
                const int ch = kk * 2 + axh;
                const uint32_t sw = arow * 256 + ((ch ^ (arow & 7)) << 4);
                ldsm_x4(bQh + sw, qhf[0], qhf[1], qhf[2], qhf[3]);
                ldsm_x4(bQl + sw, qlf[0], qlf[1], qlf[2], qlf[3]);
            }
#pragma unroll
            for (int p = 0; p < 4; p++) {
                const int row = p * 16 + brow_base;
                const int ch  = kk * 2 + bxh;
                const uint32_t sw = row * 256 + ((ch ^ (row & 7)) << 4);
                uint32_t r0, r1, r2, r3;
                ldsm_x4(bKh + sw, r0, r1, r2, r3);
                bh[p*2][0] = r0; bh[p*2][1] = r1; bh[p*2+1][0] = r2; bh[p*2+1][1] = r3;
                ldsm_x4(bKl + sw, r0, r1, r2, r3);
                bl[p*2][0] = r0; bl[p*2][1] = r1; bl[p*2+1][0] = r2; bl[p*2+1][1] = r3;
            }
#pragma unroll
            for (int nf = 0; nf < 8; nf++) {
                mma_bf16(s[nf], qhf, bh[nf]);
                mma_bf16(s[nf], qlf, bh[nf]);
                mma_bf16(s[nf], qhf, bl[nf]);
            }
        }

        if (kt * 64 + 63 > rowg0) {
            const int rowg1 = rowg0 + 8;
#pragma unroll
            for (int nf = 0; nf < 8; nf++) {
                const int c = kt * 64 + nf * 8 + (lane & 3) * 2;
                if (c     > rowg0) s[nf][0] = -1e30f;
                if (c + 1 > rowg0) s[nf][1] = -1e30f;
                if (c     > rowg1) s[nf][2] = -1e30f;
                if (c + 1 > rowg1) s[nf][3] = -1e30f;
            }
        }

        float mt0 = s[0][0], mt1 = s[0][2];
#pragma unroll
        for (int nf = 0; nf < 8; nf++) {
            mt0 = fmaxf(mt0, fmaxf(s[nf][0], s[nf][1]));
            mt1 = fmaxf(mt1, fmaxf(s[nf][2], s[nf][3]));
        }
        mt0 = fmaxf(mt0, __shfl_xor_sync(0xffffffffu, mt0, 1));
        mt0 = fmaxf(mt0, __shfl_xor_sync(0xffffffffu, mt0, 2));
        mt1 = fmaxf(mt1, __shfl_xor_sync(0xffffffffu, mt1, 1));
        mt1 = fmaxf(mt1, __shfl_xor_sync(0xffffffffu, mt1, 2));
        const float mn0 = fmaxf(m0, mt0), mn1 = fmaxf(m1, mt1);

        float lt0 = 0.f, lt1 = 0.f;
#pragma unroll
        for (int nf = 0; nf < 8; nf++) {
            s[nf][0] = __expf(s[nf][0] - mn0); lt0 += s[nf][0];
            s[nf][1] = __expf(s[nf][1] - mn0); lt0 += s[nf][1];
            s[nf][2] = __expf(s[nf][2] - mn1); lt1 += s[nf][2];
            s[nf][3] = __expf(s[nf][3] - mn1); lt1 += s[nf][3];
        }
        lt0 += __shfl_xor_sync(0xffffffffu, lt0, 1);
        lt0 += __shfl_xor_sync(0xffffffffu, lt0, 2);
        lt1 += __shfl_xor_sync(0xffffffffu, lt1, 1);
        lt1 += __shfl_xor_sync(0xffffffffu, lt1, 2);

        const float al0 = __expf(m0 - mn0), al1 = __expf(m1 - mn1);
        m0 = mn0; m1 = mn1;
        l0 = l0 * al0 + lt0; l1 = l1 * al1 + lt1;
#pragma unroll
        for (int i = 0; i < 16; i++) {
            oacc[i][0] *= al0; oacc[i][1] *= al0;
            oacc[i][2] *= al1; oacc[i][3] *= al1;
        }

        uint32_t pha[4][4], pla[4][4];
#pragma unroll
        for (int kc = 0; kc < 4; kc++) {
            const float* c0 = s[2*kc];
            const float* c1 = s[2*kc + 1];
            float h00 = __bfloat162float(__float2bfloat16_rn(c0[0]));
            float h01 = __bfloat162float(__float2bfloat16_rn(c0[1]));
            float h02 = __bfloat162float(__float2bfloat16_rn(c0[2]));
            float h03 = __bfloat162float(__float2bfloat16_rn(c0[3]));
            float h10 = __bfloat162float(__float2bfloat16_rn(c1[0]));
            float h11 = __bfloat162float(__float2bfloat16_rn(c1[1]));
            float h12 = __bfloat162float(__float2bfloat16_rn(c1[2]));
            float h13 = __bfloat162float(__float2bfloat16_rn(c1[3]));
            pha[kc][0] = pk2(c0[0], c0[1]);   pha[kc][1] = pk2(c0[2], c0[3]);
            pha[kc][2] = pk2(c1[0], c1[1]);   pha[kc][3] = pk2(c1[2], c1[3]);
            pla[kc][0] = pk2(c0[0]-h00, c0[1]-h01);
            pla[kc][1] = pk2(c0[2]-h02, c0[3]-h03);
            pla[kc][2] = pk2(c1[0]-h10, c1[1]-h11);
            pla[kc][3] = pk2(c1[2]-h12, c1[3]-h13);
        }

#pragma unroll
        for (int kc = 0; kc < 4; kc++) {
            const int krow = kc * 16 + (lane & 15);
            const uint32_t rbase = krow * 256;
            const int rxor = krow & 7;
#pragma unroll
            for (int hf = 0; hf < 2; hf++) {
                uint32_t vh[8][2], vl[8][2];
#pragma unroll
                for (int q4 = 0; q4 < 4; q4++) {
                    const int ch = hf * 8 + q4 * 2 + axh;
                    const uint32_t sw = rbase + ((ch ^ rxor) << 4);
                    uint32_t r0, r1, r2, r3;
                    ldsm_x4_t(bVh + sw, r0, r1, r2, r3);
                    vh[q4*2][0] = r0; vh[q4*2][1] = r1; vh[q4*2+1][0] = r2; vh[q4*2+1][1] = r3;
                    ldsm_x4_t(bVl + sw, r0, r1, r2, r3);
                    vl[q4*2][0] = r0; vl[q4*2][1] = r1; vl[q4*2+1][0] = r2; vl[q4*2+1][1] = r3;
                }
#pragma unroll
                for (int j = 0; j < 8; j++) {
                    const int nf2 = hf * 8 + j;
                    mma_bf16(oacc[nf2], pha[kc], vh[j]);
                    mma_bf16(oacc[nf2], pla[kc], vh[j]);
                    mma_bf16(oacc[nf2], pha[kc], vl[j]);
                }
            }
        }
    }

    // ---- epilogue: O / l -> paired hi/lo bf16 layout for the O-projection ----
    const float il0 = 1.f / l0, il1 = 1.f / l1;
    const int row = qt * 128 + wr * 16 + (lane >> 2);
    const size_t rb0 = (size_t)(b * T_ + row) * K2;
    const size_t rb1 = rb0 + (size_t)8 * K2;
    const int colbase = h * HD + (lane & 3) * 2;
#pragma unroll
    for (int nf2 = 0; nf2 < 16; nf2++) {
        const int d = colbase + nf2 * 8;
        const size_t o = (size_t)(d >> 5) * 64 + (d & 31);
        store_hl(Op, Op + 32, rb0 + o, oacc[nf2][0] * il0, oacc[nf2][1] * il0);
        store_hl(Op, Op + 32, rb1 + o, oacc[nf2][2] * il1, oacc[nf2][3] * il1);
    }
}

// ---------------- launch ----------------
extern "C" void kernel_launch(void* const* d_in, const int* in_sizes, int n_in,
                              void* d_out, int out_size)
{
    const float* x   = (const float*)d_in[0];
    const float* Wq  = (const float*)d_in[1];
    const float* Wkv = (const float*)d_in[2];
    const float* Wo  = (const float*)d_in[3];
    float* out = (float*)d_out;

    bf16 *pxp, *pwp, *pop, *pwop, *pqh, *pql, *pkh, *pkl, *pvh, *pvl;
    cudaGetSymbolAddress((void**)&pxp,  g_xp);
    cudaGetSymbolAddress((void**)&pwp,  g_wp);
    cudaGetSymbolAddress((void**)&pop,  g_op);
    cudaGetSymbolAddress((void**)&pwop, g_wop);
    cudaGetSymbolAddress((void**)&pqh,  g_qh);
    cudaGetSymbolAddress((void**)&pql,  g_ql);
    cudaGetSymbolAddress((void**)&pkh,  g_kh);
    cudaGetSymbolAddress((void**)&pkl,  g_kl);
    cudaGetSymbolAddress((void**)&pvh,  g_vh);
    cudaGetSymbolAddress((void**)&pvl,  g_vl);

    cudaFuncSetAttribute(mma_gemm2<0>, cudaFuncAttributeMaxDynamicSharedMemorySize, STAGES * 32768);
    cudaFuncSetAttribute(mma_gemm2<1>, cudaFuncAttributeMaxDynamicSharedMemorySize, STAGES * 32768);
    cudaFuncSetAttribute(flash_mma,    cudaFuncAttributeMaxDynamicSharedMemorySize, FL_SMEM);

    const int nb_x  = (B_ * T_) * (DIM_ / 32);        // 524288 blocks of 32
    const int nb_wq = DIM_ * (DIM_ / 32);
    const int nb_kv = (2 * NKV * HD) * (DIM_ / 32);

    // 0) expand operands to paired hi/lo bf16
    conv_pair<<<(nb_x  + 255) / 256, 256>>>(x,   pxp, nb_x);
    conv_pair<<<(nb_wq + 255) / 256, 256>>>(Wq,  pwp, nb_wq);
    conv_pair<<<(nb_kv + 255) / 256, 256>>>(Wkv, pwp + (size_t)DIM_ * K2, nb_kv);
    conv_pair<<<(nb_wq + 255) / 256, 256>>>(Wo,  pwop, nb_wq);

    // 1) fused QKV projection (compensated HMMA + cp.async), hi/lo scatter epilogue
    {
        dim3 grid((DIM_ + 2 * NKV * HD) / 128, (B_ * T_) / 128);   // 48 x 32
        mma_gemm2<0><<<grid, 256, STAGES * 32768>>>(pxp, pwp, nullptr,
                                                    pqh, pql, pkh, pkl, pvh, pvl);
    }

    // 2) causal GQA flash attention on tensor cores (writes paired O directly)
    {
        dim3 grid(T_ / 128, NH, B_);   // 16 x 32 x 2
        flash_mma<<<grid, 256, FL_SMEM>>>(pqh, pql, pkh, pkl, pvh, pvl, pop);
    }

    // 3) output projection
    {
        dim3 grid(DIM_ / 128, (B_ * T_) / 128);                    // 32 x 32
        mma_gemm2<1><<<grid, 256, STAGES * 32768>>>(pop, pwop, out,
                                                    nullptr, nullptr, nullptr, nullptr, nullptr, nullptr);
    }
}

// round 12
// speedup vs baseline: 1.1175x; 1.1175x over previous
#include <cuda_runtime.h>
#include <cuda_bf16.h>
#include <math.h>
#include <stdint.h>

#define B_   2
#define T_   2048
#define DIM_ 4096
#define NH   32
#define NKV  8
#define HD   128
#define RG   (NH / NKV)
#define K3   (3 * DIM_)          // 12288, triple-expanded K

#define QSCALE 0.08838834764831843f  // 1/sqrt(128)

typedef __nv_bfloat16 bf16;

// ---------------- scratch (allocation-free: __device__ globals) ----------------
__device__ bf16 g_qh[(size_t)B_ * NH  * T_ * HD];
__device__ bf16 g_ql[(size_t)B_ * NH  * T_ * HD];
__device__ bf16 g_kh[(size_t)B_ * NKV * T_ * HD];
__device__ bf16 g_kl[(size_t)B_ * NKV * T_ * HD];
__device__ bf16 g_vh[(size_t)B_ * NKV * T_ * HD];
__device__ bf16 g_vl[(size_t)B_ * NKV * T_ * HD];

// triple-expanded bf16 GEMM operands
__device__ bf16 g_x3 [(size_t)(B_*T_) * K3];
__device__ bf16 g_w13[(size_t)(DIM_ + 2*NKV*HD) * K3];
__device__ bf16 g_o3 [(size_t)(B_*T_) * K3];   // written directly by flash epilogue
__device__ bf16 g_wo3[(size_t)DIM_ * K3];

// ---------------- fp32 -> (hi,lo,hi)/(hi,hi,lo) bf16 expansion ----------------
template <bool ACT>
__global__ void __launch_bounds__(256)
conv3_kernel(const float* __restrict__ in, bf16* __restrict__ out, int n8)
{
    int i = blockIdx.x * blockDim.x + threadIdx.x;
    if (i >= n8) return;
    float4 f0 = ((const float4*)in)[(size_t)i * 2];
    float4 f1 = ((const float4*)in)[(size_t)i * 2 + 1];
    float v[8] = {f0.x, f0.y, f0.z, f0.w, f1.x, f1.y, f1.z, f1.w};
    __align__(16) bf16 o[24];
#pragma unroll
    for (int j = 0; j < 8; j++) {
        bf16 hi = __float2bfloat16_rn(v[j]);
        bf16 lo = __float2bfloat16_rn(v[j] - __bfloat162float(hi));
        if (ACT) { o[3*j] = hi; o[3*j+1] = lo; o[3*j+2] = hi; }
        else     { o[3*j] = hi; o[3*j+1] = hi; o[3*j+2] = lo; }
    }
    uint4* dst = (uint4*)(out + (size_t)i * 24);
    dst[0] = ((uint4*)o)[0];
    dst[1] = ((uint4*)o)[1];
    dst[2] = ((uint4*)o)[2];
}

// ---------------- mma helpers ----------------
__device__ __forceinline__ void ldsm_x4(uint32_t addr, uint32_t& r0, uint32_t& r1,
                                        uint32_t& r2, uint32_t& r3)
{
    asm volatile("ldmatrix.sync.aligned.m8n8.x4.shared.b16 {%0,%1,%2,%3}, [%4];"
                 : "=r"(r0), "=r"(r1), "=r"(r2), "=r"(r3) : "r"(addr));
}
__device__ __forceinline__ void ldsm_x4_t(uint32_t addr, uint32_t& r0, uint32_t& r1,
                                          uint32_t& r2, uint32_t& r3)
{
    asm volatile("ldmatrix.sync.aligned.m8n8.x4.trans.shared.b16 {%0,%1,%2,%3}, [%4];"
                 : "=r"(r0), "=r"(r1), "=r"(r2), "=r"(r3) : "r"(addr));
}
__device__ __forceinline__ void mma_bf16(float* c, const uint32_t* a, const uint32_t* b)
{
    asm volatile("mma.sync.aligned.m16n8k16.row.col.f32.bf16.bf16.f32 "
                 "{%0,%1,%2,%3}, {%4,%5,%6,%7}, {%8,%9}, {%0,%1,%2,%3};"
                 : "+f"(c[0]), "+f"(c[1]), "+f"(c[2]), "+f"(c[3])
                 : "r"(a[0]), "r"(a[1]), "r"(a[2]), "r"(a[3]), "r"(b[0]), "r"(b[1]));
}
__device__ __forceinline__ uint32_t pk2(float a, float b)
{
    __nv_bfloat162 t; t.x = __float2bfloat16_rn(a); t.y = __float2bfloat16_rn(b);
    return *reinterpret_cast<uint32_t*>(&t);
}
__device__ __forceinline__ void cp_async16(uint32_t dst, const void* src)
{
    asm volatile("cp.async.cg.shared.global [%0], [%1], 16;" :: "r"(dst), "l"(src));
}
__device__ __forceinline__ void cp_commit() { asm volatile("cp.async.commit_group;"); }
__device__ __forceinline__ void cp_wait1()  { asm volatile("cp.async.wait_group 1;"); }

// ---------------- epilogue stores ----------------
__device__ __forceinline__ void store_hl(bf16* __restrict__ hi, bf16* __restrict__ lo,
                                         size_t idx, float v0, float v1)
{
    bf16 h0 = __float2bfloat16_rn(v0), h1 = __float2bfloat16_rn(v1);
    bf16 e0 = __float2bfloat16_rn(v0 - __bfloat162float(h0));
    bf16 e1 = __float2bfloat16_rn(v1 - __bfloat162float(h1));
    __nv_bfloat162 H; H.x = h0; H.y = h1;
    __nv_bfloat162 L; L.x = e0; L.y = e1;
    *(__nv_bfloat162*)(hi + idx) = H;
    *(__nv_bfloat162*)(lo + idx) = L;
}

__device__ __forceinline__ void scatter2(int m, int n, float v0, float v1,
                                         bf16* qh, bf16* ql, bf16* kh, bf16* kl,
                                         bf16* vh, bf16* vl)
{
    const int bb = m >> 11;
    const int t  = m & (T_ - 1);
    if (n < DIM_) {
        size_t idx = (((size_t)bb * NH + (n >> 7)) * T_ + t) * HD + (n & 127);
        store_hl(qh, ql, idx, v0 * QSCALE, v1 * QSCALE);
    } else {
        int cc = n - DIM_;
        if (cc < NKV * HD) {
            size_t idx = (((size_t)bb * NKV + (cc >> 7)) * T_ + t) * HD + (cc & 127);
            store_hl(kh, kl, idx, v0, v1);
        } else {
            cc -= NKV * HD;
            size_t idx = (((size_t)bb * NKV + (cc >> 7)) * T_ + t) * HD + (cc & 127);
            store_hl(vh, vl, idx, v0, v1);
        }
    }
}

// ---------------- tensor-core bf16 GEMM (validated round-8): C = A3 @ W3^T ----------------
template <int MODE>
__global__ void __launch_bounds__(256)
mma_gemm(const bf16* __restrict__ A, const bf16* __restrict__ W,
         float* __restrict__ outC,
         bf16* qh, bf16* ql, bf16* kh, bf16* kl, bf16* vh, bf16* vl)
{
    extern __shared__ __align__(16) unsigned char smem[];   // 2 * (16KB A + 16KB B)

    const int tid  = threadIdx.x;
    const int lane = tid & 31;
    const int w    = tid >> 5;
    const int wm   = w & 1;
    const int wn   = w >> 1;
    const int m0   = blockIdx.y * 128;
    const int n0   = blockIdx.x * 128;

    const int lr   = tid >> 3;
    const int lc   = tid & 7;
    const int sc16 = ((lc ^ (lr & 7)) << 4);

    const bf16* Ag = A + (size_t)(m0 + lr) * K3 + lc * 8;
    const bf16* Wg = W + (size_t)(n0 + lr) * K3 + lc * 8;

    float acc[4][4][4];
#pragma unroll
    for (int i = 0; i < 4; i++)
#pragma unroll
        for (int j = 0; j < 4; j++)
#pragma unroll
            for (int e = 0; e < 4; e++) acc[i][j][e] = 0.f;

    uint4 pa[4], pb[4];
#pragma unroll
    for (int u = 0; u < 4; u++) {
        pa[u] = *(const uint4*)(Ag + (size_t)(32 * u) * K3);
        pb[u] = *(const uint4*)(Wg + (size_t)(32 * u) * K3);
    }

    const int rA  = lane & 15;
    const int cAh = lane >> 4;
    const int rB  = (lane & 7) + ((lane >> 4) << 3);
    const int cBh = (lane >> 3) & 1;

    for (int k0 = 0; k0 < K3; k0 += 64) {
        unsigned char* sa = smem + (((k0 >> 6) & 1) * 32768);
        unsigned char* sb = sa + 16384;

#pragma unroll
        for (int u = 0; u < 4; u++) {
            *(uint4*)(sa + (lr + 32 * u) * 128 + sc16) = pa[u];
            *(uint4*)(sb + (lr + 32 * u) * 128 + sc16) = pb[u];
        }
        __syncthreads();

        if (k0 + 64 < K3) {
#pragma unroll
            for (int u = 0; u < 4; u++) {
                pa[u] = *(const uint4*)(Ag + (size_t)(32 * u) * K3 + k0 + 64);
                pb[u] = *(const uint4*)(Wg + (size_t)(32 * u) * K3 + k0 + 64);
            }
        }

        const uint32_t saddr = (uint32_t)__cvta_generic_to_shared(sa);
        const uint32_t sbddr = saddr + 16384;

#pragma unroll
        for (int kk = 0; kk < 4; kk++) {
            uint32_t a[4][4], b[4][2];
#pragma unroll
            for (int mi = 0; mi < 4; mi++) {
                const int row = wm * 64 + mi * 16 + rA;
                const int ch  = kk * 2 + cAh;
                const uint32_t addr = saddr + row * 128 + ((ch ^ (row & 7)) << 4);
                ldsm_x4(addr, a[mi][0], a[mi][1], a[mi][2], a[mi][3]);
            }
#pragma unroll
            for (int np = 0; np < 2; np++) {
                const int row = wn * 32 + np * 16 + rB;
                const int ch  = kk * 2 + cBh;
                const uint32_t addr = sbddr + row * 128 + ((ch ^ (row & 7)) << 4);
                uint32_t r0, r1, r2, r3;
                ldsm_x4(addr, r0, r1, r2, r3);
                b[np * 2][0] = r0; b[np * 2][1] = r1;
                b[np * 2 + 1][0] = r2; b[np * 2 + 1][1] = r3;
            }
#pragma unroll
            for (int mi = 0; mi < 4; mi++)
#pragma unroll
                for (int ni = 0; ni < 4; ni++)
                    mma_bf16(acc[mi][ni], a[mi], b[ni]);
        }
    }

    const int er = lane >> 2;
    const int ec = (lane & 3) * 2;
#pragma unroll
    for (int mi = 0; mi < 4; mi++) {
        const int m = m0 + wm * 64 + mi * 16 + er;
#pragma unroll
        for (int ni = 0; ni < 4; ni++) {
            const int n = n0 + wn * 32 + ni * 8 + ec;
            if (MODE == 1) {
                *(float2*)(outC + (size_t)m * DIM_ + n)       = make_float2(acc[mi][ni][0], acc[mi][ni][1]);
                *(float2*)(outC + (size_t)(m + 8) * DIM_ + n) = make_float2(acc[mi][ni][2], acc[mi][ni][3]);
            } else {
                scatter2(m,     n, acc[mi][ni][0], acc[mi][ni][1], qh, ql, kh, kl, vh, vl);
                scatter2(m + 8, n, acc[mi][ni][2], acc[mi][ni][3], qh, ql, kh, kl, vh, vl);
            }
        }
    }
}

// ---------------- tensor-core flash attention (compensated bf16, cp.async 2-stage KV) ----------------
// Br=128 (8 warps x 16 rows), Bc=64, hd=128.
// smem: Qh 32K | Ql 32K | 2 x (Kh 16K | Kl 16K | Vh 16K | Vl 16K) = 192KB
#define FL_SMEM 196608

__global__ void __launch_bounds__(256)
flash_mma(const bf16* __restrict__ Qh, const bf16* __restrict__ Ql,
          const bf16* __restrict__ Kh, const bf16* __restrict__ Kl,
          const bf16* __restrict__ Vh, const bf16* __restrict__ Vl,
          bf16* __restrict__ O3)       // triple-expanded (hi,lo,hi) output
{
    extern __shared__ __align__(16) unsigned char sm[];
    const uint32_t sb  = (uint32_t)__cvta_generic_to_shared(sm);
    const uint32_t bQh = sb, bQl = sb + 32768;
    const uint32_t bKV = sb + 65536;        // + buf*65536: Kh|Kl|Vh|Vl (16K each)

    const int qt = (T_ / 128 - 1) - blockIdx.x;   // longest-first scheduling
    const int h = blockIdx.y, b = blockIdx.z;
    const int g  = h / RG;
    const int tid = threadIdx.x, lane = tid & 31, wr = tid >> 5;

    const bf16* khg = Kh + (((size_t)b * NKV + g) * T_) * HD;
    const bf16* klg = Kl + (((size_t)b * NKV + g) * T_) * HD;
    const bf16* vhg = Vh + (((size_t)b * NKV + g) * T_) * HD;
    const bf16* vlg = Vl + (((size_t)b * NKV + g) * T_) * HD;

    // per-thread staging geometry (row = s>>4, chunk = s&15, 64-row KV tiles)
    const int ktmax = 2 * qt + 1;

    // ---- prologue: async Q (hi+lo) + KV tile 0 into buf 0, one group ----
    {
        const bf16* qhg = Qh + (((size_t)b * NH + h) * T_ + (size_t)qt * 128) * HD;
        const bf16* qlg = Ql + (((size_t)b * NH + h) * T_ + (size_t)qt * 128) * HD;
#pragma unroll
        for (int u = 0; u < 8; u++) {
            const int s = tid + 256 * u;
            const int row = s >> 4, ch = s & 15;
            const uint32_t so = row * 256 + ((ch ^ (row & 7)) << 4);
            const int go = row * HD + ch * 8;
            cp_async16(bQh + so, qhg + go);
            cp_async16(bQl + so, qlg + go);
        }
#pragma unroll
        for (int u = 0; u < 4; u++) {
            const int s = tid + 256 * u;
            const int row = s >> 4, ch = s & 15;
            const uint32_t so = row * 256 + ((ch ^ (row & 7)) << 4);
            const int go = row * HD + ch * 8;
            cp_async16(bKV + so,         khg + go);
            cp_async16(bKV + 16384 + so, klg + go);
            cp_async16(bKV + 32768 + so, vhg + go);
            cp_async16(bKV + 49152 + so, vlg + go);
        }
        cp_commit();
    }

    float oacc[16][4];
#pragma unroll
    for (int i = 0; i < 16; i++)
#pragma unroll
        for (int e = 0; e < 4; e++) oacc[i][e] = 0.f;
    float m0 = -1e30f, m1 = -1e30f, l0 = 0.f, l1 = 0.f;

    const int arow = wr * 16 + (lane & 15);
    const int axh  = lane >> 4;
    const int bxh  = (lane >> 3) & 1;
    const int brow_base = (lane & 7) + ((lane >> 4) << 3);
    const int rowg0 = qt * 128 + wr * 16 + (lane >> 2);

    for (int kt = 0; kt <= ktmax; kt++) {
        __syncthreads();   // all warps done computing from buf[(kt+1)&1] (iter kt-1)
        if (kt + 1 <= ktmax) {
            const uint32_t st = bKV + (uint32_t)((kt + 1) & 1) * 65536u;
            const size_t base = (size_t)(kt + 1) * 64 * HD;
#pragma unroll
            for (int u = 0; u < 4; u++) {
                const int s = tid + 256 * u;
                const int row = s >> 4, ch = s & 15;
                const uint32_t so = row * 256 + ((ch ^ (row & 7)) << 4);
                const size_t go = base + row * HD + ch * 8;
                cp_async16(st + so,         khg + go);
                cp_async16(st + 16384 + so, klg + go);
                cp_async16(st + 32768 + so, vhg + go);
                cp_async16(st + 49152 + so, vlg + go);
            }
        }
        cp_commit();
        cp_wait1();        // tile kt (and Q on kt=0) has landed; kt+1 in flight
        __syncthreads();

        if (kt * 64 > qt * 128 + wr * 16 + 15) continue;   // fully-masked warp

        const uint32_t cKh = bKV + (uint32_t)(kt & 1) * 65536u;
        const uint32_t cKl = cKh + 16384, cVh = cKh + 32768, cVl = cKh + 49152;

        // ---- S = Q K^T (3 compensated passes) ----
        float s[8][4];
#pragma unroll
        for (int nf = 0; nf < 8; nf++)
#pragma unroll
            for (int e = 0; e < 4; e++) s[nf][e] = 0.f;

#pragma unroll
        for (int kk = 0; kk < 8; kk++) {
            uint32_t qhf[4], qlf[4], bh[8][2], bl[8][2];
            {
                const int ch = kk * 2 + axh;
                const uint32_t sw = arow * 256 + ((ch ^ (arow & 7)) << 4);
                ldsm_x4(bQh + sw, qhf[0], qhf[1], qhf[2], qhf[3]);
                ldsm_x4(bQl + sw, qlf[0], qlf[1], qlf[2], qlf[3]);
            }
#pragma unroll
            for (int p = 0; p < 4; p++) {
                const int row = p * 16 + brow_base;
                const int ch  = kk * 2 + bxh;
                const uint32_t sw = row * 256 + ((ch ^ (row & 7)) << 4);
                uint32_t r0, r1, r2, r3;
                ldsm_x4(cKh + sw, r0, r1, r2, r3);
                bh[p*2][0] = r0; bh[p*2][1] = r1; bh[p*2+1][0] = r2; bh[p*2+1][1] = r3;
                ldsm_x4(cKl + sw, r0, r1, r2, r3);
                bl[p*2][0] = r0; bl[p*2][1] = r1; bl[p*2+1][0] = r2; bl[p*2+1][1] = r3;
            }
#pragma unroll
            for (int nf = 0; nf < 8; nf++) {
                mma_bf16(s[nf], qhf, bh[nf]);
                mma_bf16(s[nf], qlf, bh[nf]);
                mma_bf16(s[nf], qhf, bl[nf]);
            }
        }

        if (kt * 64 + 63 > rowg0) {
            const int rowg1 = rowg0 + 8;
#pragma unroll
            for (int nf = 0; nf < 8; nf++) {
                const int c = kt * 64 + nf * 8 + (lane & 3) * 2;
                if (c     > rowg0) s[nf][0] = -1e30f;
                if (c + 1 > rowg0) s[nf][1] = -1e30f;
                if (c     > rowg1) s[nf][2] = -1e30f;
                if (c + 1 > rowg1) s[nf][3] = -1e30f;
            }
        }

        float mt0 = s[0][0], mt1 = s[0][2];
#pragma unroll
        for (int nf = 0; nf < 8; nf++) {
            mt0 = fmaxf(mt0, fmaxf(s[nf][0], s[nf][1]));
            mt1 = fmaxf(mt1, fmaxf(s[nf][2], s[nf][3]));
        }
        mt0 = fmaxf(mt0, __shfl_xor_sync(0xffffffffu, mt0, 1));
        mt0 = fmaxf(mt0, __shfl_xor_sync(0xffffffffu, mt0, 2));
        mt1 = fmaxf(mt1, __shfl_xor_sync(0xffffffffu, mt1, 1));
        mt1 = fmaxf(mt1, __shfl_xor_sync(0xffffffffu, mt1, 2));
        const float mn0 = fmaxf(m0, mt0), mn1 = fmaxf(m1, mt1);

        float lt0 = 0.f, lt1 = 0.f;
#pragma unroll
        for (int nf = 0; nf < 8; nf++) {
            s[nf][0] = __expf(s[nf][0] - mn0); lt0 += s[nf][0];
            s[nf][1] = __expf(s[nf][1] - mn0); lt0 += s[nf][1];
            s[nf][2] = __expf(s[nf][2] - mn1); lt1 += s[nf][2];
            s[nf][3] = __expf(s[nf][3] - mn1); lt1 += s[nf][3];
        }
        lt0 += __shfl_xor_sync(0xffffffffu, lt0, 1);
        lt0 += __shfl_xor_sync(0xffffffffu, lt0, 2);
        lt1 += __shfl_xor_sync(0xffffffffu, lt1, 1);
        lt1 += __shfl_xor_sync(0xffffffffu, lt1, 2);

        const float al0 = __expf(m0 - mn0), al1 = __expf(m1 - mn1);
        m0 = mn0; m1 = mn1;
        l0 = l0 * al0 + lt0; l1 = l1 * al1 + lt1;
#pragma unroll
        for (int i = 0; i < 16; i++) {
            oacc[i][0] *= al0; oacc[i][1] *= al0;
            oacc[i][2] *= al1; oacc[i][3] *= al1;
        }

        uint32_t pha[4][4], pla[4][4];
#pragma unroll
        for (int kc = 0; kc < 4; kc++) {
            const float* c0 = s[2*kc];
            const float* c1 = s[2*kc + 1];
            float h00 = __bfloat162float(__float2bfloat16_rn(c0[0]));
            float h01 = __bfloat162float(__float2bfloat16_rn(c0[1]));
            float h02 = __bfloat162float(__float2bfloat16_rn(c0[2]));
            float h03 = __bfloat162float(__float2bfloat16_rn(c0[3]));
            float h10 = __bfloat162float(__float2bfloat16_rn(c1[0]));
            float h11 = __bfloat162float(__float2bfloat16_rn(c1[1]));
            float h12 = __bfloat162float(__float2bfloat16_rn(c1[2]));
            float h13 = __bfloat162float(__float2bfloat16_rn(c1[3]));
            pha[kc][0] = pk2(c0[0], c0[1]);   pha[kc][1] = pk2(c0[2], c0[3]);
            pha[kc][2] = pk2(c1[0], c1[1]);   pha[kc][3] = pk2(c1[2], c1[3]);
            pla[kc][0] = pk2(c0[0]-h00, c0[1]-h01);
            pla[kc][1] = pk2(c0[2]-h02, c0[3]-h03);
            pla[kc][2] = pk2(c1[0]-h10, c1[1]-h11);
            pla[kc][3] = pk2(c1[2]-h12, c1[3]-h13);
        }

#pragma unroll
        for (int kc = 0; kc < 4; kc++) {
            const int krow = kc * 16 + (lane & 15);
            const uint32_t rbase = krow * 256;
            const int rxor = krow & 7;
#pragma unroll
            for (int hf = 0; hf < 2; hf++) {
                uint32_t vh[8][2], vl[8][2];
#pragma unroll
                for (int q4 = 0; q4 < 4; q4++) {
                    const int ch = hf * 8 + q4 * 2 + axh;
                    const uint32_t sw = rbase + ((ch ^ rxor) << 4);
                    uint32_t r0, r1, r2, r3;
                    ldsm_x4_t(cVh + sw, r0, r1, r2, r3);
                    vh[q4*2][0] = r0; vh[q4*2][1] = r1; vh[q4*2+1][0] = r2; vh[q4*2+1][1] = r3;
                    ldsm_x4_t(cVl + sw, r0, r1, r2, r3);
                    vl[q4*2][0] = r0; vl[q4*2][1] = r1; vl[q4*2+1][0] = r2; vl[q4*2+1][1] = r3;
                }
#pragma unroll
                for (int j = 0; j < 8; j++) {
                    const int nf2 = hf * 8 + j;
                    mma_bf16(oacc[nf2], pha[kc], vh[j]);
                    mma_bf16(oacc[nf2], pla[kc], vh[j]);
                    mma_bf16(oacc[nf2], pha[kc], vl[j]);
                }
            }
        }
    }

    // ---- epilogue: O / l -> triple-expanded (hi,lo,hi) g_o3 directly ----
    const float il0 = 1.f / l0, il1 = 1.f / l1;
    const int row = qt * 128 + wr * 16 + (lane >> 2);
    bf16* r0p = O3 + (size_t)(b * T_ + row) * K3;
    bf16* r1p = r0p + (size_t)8 * K3;
    const int colbase = h * HD + (lane & 3) * 2;
#pragma unroll
    for (int nf2 = 0; nf2 < 16; nf2++) {
        const int d = colbase + nf2 * 8;
        {
            float v0 = oacc[nf2][0] * il0, v1 = oacc[nf2][1] * il0;
            bf16 h0 = __float2bfloat16_rn(v0), h1 = __float2bfloat16_rn(v1);
            bf16 e0 = __float2bfloat16_rn(v0 - __bfloat162float(h0));
            bf16 e1 = __float2bfloat16_rn(v1 - __bfloat162float(h1));
            uint32_t u0 = (uint32_t)*(uint16_t*)&h0 | ((uint32_t)*(uint16_t*)&e0 << 16);
            uint32_t u1 = (uint32_t)*(uint16_t*)&h0 | ((uint32_t)*(uint16_t*)&h1 << 16);
            uint32_t u2 = (uint32_t)*(uint16_t*)&e1 | ((uint32_t)*(uint16_t*)&h1 << 16);
            uint32_t* p = (uint32_t*)(r0p + 3 * d);
            p[0] = u0; p[1] = u1; p[2] = u2;
        }
        {
            float v0 = oacc[nf2][2] * il1, v1 = oacc[nf2][3] * il1;
            bf16 h0 = __float2bfloat16_rn(v0), h1 = __float2bfloat16_rn(v1);
            bf16 e0 = __float2bfloat16_rn(v0 - __bfloat162float(h0));
            bf16 e1 = __float2bfloat16_rn(v1 - __bfloat162float(h1));
            uint32_t u0 = (uint32_t)*(uint16_t*)&h0 | ((uint32_t)*(uint16_t*)&e0 << 16);
            uint32_t u1 = (uint32_t)*(uint16_t*)&h0 | ((uint32_t)*(uint16_t*)&h1 << 16);
            uint32_t u2 = (uint32_t)*(uint16_t*)&e1 | ((uint32_t)*(uint16_t*)&h1 << 16);
            uint32_t* p = (uint32_t*)(r1p + 3 * d);
            p[0] = u0; p[1] = u1; p[2] = u2;
        }
    }
}

// ---------------- launch ----------------
extern "C" void kernel_launch(void* const* d_in, const int* in_sizes, int n_in,
                              void* d_out, int out_size)
{
    const float* x   = (const float*)d_in[0];
    const float* Wq  = (const float*)d_in[1];
    const float* Wkv = (const float*)d_in[2];
    const float* Wo  = (const float*)d_in[3];
    float* out = (float*)d_out;

    bf16 *pqh, *pql, *pkh, *pkl, *pvh, *pvl, *px3, *pw13, *po3, *pwo3;
    cudaGetSymbolAddress((void**)&pqh,  g_qh);
    cudaGetSymbolAddress((void**)&pql,  g_ql);
    cudaGetSymbolAddress((void**)&pkh,  g_kh);
    cudaGetSymbolAddress((void**)&pkl,  g_kl);
    cudaGetSymbolAddress((void**)&pvh,  g_vh);
    cudaGetSymbolAddress((void**)&pvl,  g_vl);
    cudaGetSymbolAddress((void**)&px3,  g_x3);
    cudaGetSymbolAddress((void**)&pw13, g_w13);
    cudaGetSymbolAddress((void**)&po3,  g_o3);
    cudaGetSymbolAddress((void**)&pwo3, g_wo3);

    cudaFuncSetAttribute(mma_gemm<0>, cudaFuncAttributeMaxDynamicSharedMemorySize, 65536);
    cudaFuncSetAttribute(mma_gemm<1>, cudaFuncAttributeMaxDynamicSharedMemorySize, 65536);
    cudaFuncSetAttribute(flash_mma,   cudaFuncAttributeMaxDynamicSharedMemorySize, FL_SMEM);

    const int n8_x  = (B_ * T_) * (DIM_ / 8);
    const int n8_wq = DIM_ * (DIM_ / 8);
    const int n8_kv = (2 * NKV * HD) * (DIM_ / 8);

    // 0) expand operands to compensated bf16 triples
    conv3_kernel<true ><<<(n8_x  + 255) / 256, 256>>>(x,   px3, n8_x);
    conv3_kernel<false><<<(n8_wq + 255) / 256, 256>>>(Wq,  pw13, n8_wq);
    conv3_kernel<false><<<(n8_kv + 255) / 256, 256>>>(Wkv, pw13 + (size_t)DIM_ * K3, n8_kv);
    conv3_kernel<false><<<(n8_wq + 255) / 256, 256>>>(Wo,  pwo3, n8_wq);

    // 1) fused QKV projection (tensor cores), hi/lo bf16 scatter epilogue
    {
        dim3 grid((DIM_ + 2 * NKV * HD) / 128, (B_ * T_) / 128);   // 48 x 32
        mma_gemm<0><<<grid, 256, 65536>>>(px3, pw13, nullptr, pqh, pql, pkh, pkl, pvh, pvl);
    }

    // 2) causal GQA flash attention (writes triple-expanded O directly)
    {
        dim3 grid(T_ / 128, NH, B_);   // 16 x 32 x 2
        flash_mma<<<grid, 256, FL_SMEM>>>(pqh, pql, pkh, pkl, pvh, pvl, po3);
    }

    // 3) output projection (tensor cores)
    {
        dim3 grid(DIM_ / 128, (B_ * T_) / 128);                    // 32 x 32
        mma_gemm<1><<<grid, 256, 65536>>>(po3, pwo3, out, nullptr, nullptr, nullptr, nullptr, nullptr, nullptr);
    }
}